// round 2
// baseline (speedup 1.0000x reference)
#include <cuda_runtime.h>

#define N_NODES 50000
#define N_EDGES 600000
#define REL_NUM 500
#define E_HID   128

// output layout: x_e [50000*128] | rel_out [500*128] | res_att [600000]
#define REL_OFF (N_NODES * E_HID)
#define RES_OFF (REL_OFF + REL_NUM * E_HID)

// scratch (device globals: no allocations allowed)
__device__ float    g_remb[REL_NUM * E_HID];  // r_emb = rel_emb @ ww_w.T
__device__ float    g_dp[N_EDGES];            // per-edge dot products
__device__ unsigned g_max_bits;               // order-encoded float max
__device__ float    g_sum;                    // softmax denominator

// order-preserving float<->uint encoding for atomicMax on floats
__device__ __forceinline__ unsigned enc_f(float f) {
    unsigned u = __float_as_uint(f);
    return (u & 0x80000000u) ? ~u : (u | 0x80000000u);
}
__device__ __forceinline__ float dec_f(unsigned u) {
    return (u & 0x80000000u) ? __uint_as_float(u & 0x7FFFFFFFu)
                             : __uint_as_float(~u);
}

// ---------------------------------------------------------------------------
// K0: zero x_e region, copy res_att through, reset reduction scalars
// ---------------------------------------------------------------------------
__global__ void k_init(float* __restrict__ out, const float* __restrict__ res_att) {
    int i = blockIdx.x * blockDim.x + threadIdx.x;
    int stride = gridDim.x * blockDim.x;
    for (int j = i; j < N_NODES * E_HID; j += stride) out[j] = 0.f;
    for (int j = i; j < N_EDGES; j += stride) out[RES_OFF + j] = res_att[j];
    if (i == 0) { g_max_bits = 0u; g_sum = 0.f; }
}

// ---------------------------------------------------------------------------
// K1: r_emb = rel_emb @ ww_w.T (scratch);  rel_out = rel_emb @ rel_w.T (out)
// ---------------------------------------------------------------------------
__global__ void k_rel(const float* __restrict__ rel_emb,
                      const float* __restrict__ ww_w,
                      const float* __restrict__ rel_w,
                      float* __restrict__ out) {
    __shared__ float row[E_HID];
    int r = blockIdx.x, t = threadIdx.x;
    row[t] = rel_emb[r * E_HID + t];
    __syncthreads();
    float a = 0.f, b = 0.f;
#pragma unroll 8
    for (int k = 0; k < E_HID; k++) {
        float v = row[k];
        a = fmaf(v, ww_w[t * E_HID + k], a);
        b = fmaf(v, rel_w[t * E_HID + k], b);
    }
    g_remb[r * E_HID + t] = a;
    out[REL_OFF + r * E_HID + t] = b;
}

// ---------------------------------------------------------------------------
// K2: per-edge dot product. One warp per edge; lane handles 4 contiguous
// floats (float4), warp shuffle reduce.  Indices are INT32 (JAX x64 disabled).
// ---------------------------------------------------------------------------
__global__ void k_dp(const float* __restrict__ x,
                     const int* __restrict__ ei,
                     const int* __restrict__ et) {
    int e = (int)(((long long)blockIdx.x * blockDim.x + threadIdx.x) >> 5);
    int lane = threadIdx.x & 31;
    if (e >= N_EDGES) return;
    int src = ei[e];
    int dst = ei[N_EDGES + e];
    int r = et[e];
    const float4 xs = *(const float4*)(x + (long long)src * E_HID + lane * 4);
    const float4 rr = *(const float4*)(g_remb + (long long)r * E_HID + lane * 4);
    const float4 xt = *(const float4*)(x + (long long)dst * E_HID + lane * 4);
    float p = (xs.x + rr.x) * xt.x + (xs.y + rr.y) * xt.y
            + (xs.z + rr.z) * xt.z + (xs.w + rr.w) * xt.w;
#pragma unroll
    for (int o = 16; o; o >>= 1) p += __shfl_xor_sync(0xffffffffu, p, o);
    if (lane == 0) g_dp[e] = p;
}

// ---------------------------------------------------------------------------
// K3: global max of g_dp
// ---------------------------------------------------------------------------
__global__ void k_max() {
    float m = -3.4e38f;
    int i = blockIdx.x * blockDim.x + threadIdx.x;
    int stride = gridDim.x * blockDim.x;
    for (int j = i; j < N_EDGES; j += stride) m = fmaxf(m, g_dp[j]);
#pragma unroll
    for (int o = 16; o; o >>= 1) m = fmaxf(m, __shfl_xor_sync(0xffffffffu, m, o));
    __shared__ float sm[32];
    if ((threadIdx.x & 31) == 0) sm[threadIdx.x >> 5] = m;
    __syncthreads();
    if (threadIdx.x < 32) {
        m = (threadIdx.x < (blockDim.x >> 5)) ? sm[threadIdx.x] : -3.4e38f;
#pragma unroll
        for (int o = 16; o; o >>= 1) m = fmaxf(m, __shfl_xor_sync(0xffffffffu, m, o));
        if (threadIdx.x == 0) atomicMax(&g_max_bits, enc_f(m));
    }
}

// ---------------------------------------------------------------------------
// K4: softmax denominator sum(exp(dp - max))
// ---------------------------------------------------------------------------
__global__ void k_sum() {
    float m = dec_f(g_max_bits);
    float s = 0.f;
    int i = blockIdx.x * blockDim.x + threadIdx.x;
    int stride = gridDim.x * blockDim.x;
    for (int j = i; j < N_EDGES; j += stride) s += __expf(g_dp[j] - m);
#pragma unroll
    for (int o = 16; o; o >>= 1) s += __shfl_xor_sync(0xffffffffu, s, o);
    __shared__ float sm[32];
    if ((threadIdx.x & 31) == 0) sm[threadIdx.x >> 5] = s;
    __syncthreads();
    if (threadIdx.x < 32) {
        s = (threadIdx.x < (blockDim.x >> 5)) ? sm[threadIdx.x] : 0.f;
#pragma unroll
        for (int o = 16; o; o >>= 1) s += __shfl_xor_sync(0xffffffffu, s, o);
        if (threadIdx.x == 0) atomicAdd(&g_sum, s);
    }
}

// ---------------------------------------------------------------------------
// K5: weighted scatter-add. One warp per edge; recompute h_r = x[src]+r_emb,
// scale by softmax coef, atomicAdd into x_e[dst].
// ---------------------------------------------------------------------------
__global__ void k_scatter(const float* __restrict__ x,
                          const int* __restrict__ ei,
                          const int* __restrict__ et,
                          float* __restrict__ out) {
    int e = (int)(((long long)blockIdx.x * blockDim.x + threadIdx.x) >> 5);
    int lane = threadIdx.x & 31;
    if (e >= N_EDGES) return;
    float m = dec_f(g_max_bits);
    float inv = 1.0f / g_sum;
    float coef = __expf(g_dp[e] - m) * inv;
    int src = ei[e];
    int dst = ei[N_EDGES + e];
    int r = et[e];
    const float4 xs = *(const float4*)(x + (long long)src * E_HID + lane * 4);
    const float4 rr = *(const float4*)(g_remb + (long long)r * E_HID + lane * 4);
    float* p = out + (long long)dst * E_HID + lane * 4;
    atomicAdd(p + 0, coef * (xs.x + rr.x));
    atomicAdd(p + 1, coef * (xs.y + rr.y));
    atomicAdd(p + 2, coef * (xs.z + rr.z));
    atomicAdd(p + 3, coef * (xs.w + rr.w));
}

// ---------------------------------------------------------------------------
// K6: in-place ReLU on x_e
// ---------------------------------------------------------------------------
__global__ void k_relu(float* __restrict__ out) {
    int i = blockIdx.x * blockDim.x + threadIdx.x;
    int stride = gridDim.x * blockDim.x;
    for (int j = i; j < N_NODES * E_HID; j += stride)
        out[j] = fmaxf(out[j], 0.f);
}

extern "C" void kernel_launch(void* const* d_in, const int* in_sizes, int n_in,
                              void* d_out, int out_size) {
    const float* x       = (const float*)d_in[0];   // [50000,128] f32
    const int*   ei      = (const int*)d_in[1];     // [2,600000] int32 (JAX x64 off)
    const int*   et      = (const int*)d_in[2];     // [600000] int32
    const float* rel_emb = (const float*)d_in[3];   // [500,128]
    const float* res_att = (const float*)d_in[4];   // [600000]
    const float* ww_w    = (const float*)d_in[5];   // [128,128]
    const float* rel_w   = (const float*)d_in[6];   // [128,128]
    float* out = (float*)d_out;

    (void)in_sizes; (void)n_in; (void)out_size;

    k_init<<<4096, 256>>>(out, res_att);
    k_rel<<<REL_NUM, E_HID>>>(rel_emb, ww_w, rel_w, out);

    const int edge_blocks = (N_EDGES * 32 + 255) / 256;  // warp per edge
    k_dp<<<edge_blocks, 256>>>(x, ei, et);
    k_max<<<512, 256>>>();
    k_sum<<<512, 256>>>();
    k_scatter<<<edge_blocks, 256>>>(x, ei, et, out);
    k_relu<<<4096, 256>>>(out);
}

// round 3
// speedup vs baseline: 1.4530x; 1.4530x over previous
#include <cuda_runtime.h>

#define N_NODES 50000
#define N_EDGES 600000
#define REL_NUM 500
#define E_HID   128

// output layout: x_e [50000*128] | rel_out [500*128] | res_att [600000]
#define REL_OFF (N_NODES * E_HID)
#define RES_OFF (REL_OFF + REL_NUM * E_HID)

// scratch (device globals: no allocations allowed)
__device__ float    g_remb[REL_NUM * E_HID];  // r_emb = rel_emb @ ww_w.T
__device__ float    g_dp[N_EDGES];            // per-edge dot products
__device__ unsigned g_max_bits;               // order-encoded float max
__device__ float    g_sum;                    // softmax denominator

__device__ __forceinline__ unsigned enc_f(float f) {
    unsigned u = __float_as_uint(f);
    return (u & 0x80000000u) ? ~u : (u | 0x80000000u);
}
__device__ __forceinline__ float dec_f(unsigned u) {
    return (u & 0x80000000u) ? __uint_as_float(u & 0x7FFFFFFFu)
                             : __uint_as_float(~u);
}

// vectorized global reduction: one RED.128 instead of four RED.32
__device__ __forceinline__ void red_add_v4(float* p, float a, float b, float c, float d) {
    asm volatile("red.global.add.v4.f32 [%0], {%1, %2, %3, %4};"
                 :: "l"(p), "f"(a), "f"(b), "f"(c), "f"(d) : "memory");
}

// ---------------------------------------------------------------------------
// K0: zero x_e region (float4), copy res_att through, reset scalars
// ---------------------------------------------------------------------------
__global__ void k_init(float* __restrict__ out, const float* __restrict__ res_att) {
    int i = blockIdx.x * blockDim.x + threadIdx.x;
    int stride = gridDim.x * blockDim.x;
    float4 z = make_float4(0.f, 0.f, 0.f, 0.f);
    float4* o4 = (float4*)out;
    for (int j = i; j < (N_NODES * E_HID) / 4; j += stride) o4[j] = z;
    for (int j = i; j < N_EDGES; j += stride) out[RES_OFF + j] = res_att[j];
    if (i == 0) { g_max_bits = 0u; g_sum = 0.f; }
}

// ---------------------------------------------------------------------------
// K1: r_emb = rel_emb @ ww_w.T (scratch);  rel_out = rel_emb @ rel_w.T (out)
// ---------------------------------------------------------------------------
__global__ void k_rel(const float* __restrict__ rel_emb,
                      const float* __restrict__ ww_w,
                      const float* __restrict__ rel_w,
                      float* __restrict__ out) {
    __shared__ float row[E_HID];
    int r = blockIdx.x, t = threadIdx.x;
    row[t] = rel_emb[r * E_HID + t];
    __syncthreads();
    float a = 0.f, b = 0.f;
#pragma unroll 8
    for (int k = 0; k < E_HID; k++) {
        float v = row[k];
        a = fmaf(v, ww_w[t * E_HID + k], a);
        b = fmaf(v, rel_w[t * E_HID + k], b);
    }
    g_remb[r * E_HID + t] = a;
    out[REL_OFF + r * E_HID + t] = b;
}

// ---------------------------------------------------------------------------
// K2: per-edge dot product. One warp per edge, float4 per lane.
// ---------------------------------------------------------------------------
__global__ void k_dp(const float* __restrict__ x,
                     const int* __restrict__ ei,
                     const int* __restrict__ et) {
    int e = (int)(((long long)blockIdx.x * blockDim.x + threadIdx.x) >> 5);
    int lane = threadIdx.x & 31;
    if (e >= N_EDGES) return;
    int src = ei[e];
    int dst = ei[N_EDGES + e];
    int r = et[e];
    const float4 xs = *(const float4*)(x + (long long)src * E_HID + lane * 4);
    const float4 rr = *(const float4*)(g_remb + (long long)r * E_HID + lane * 4);
    const float4 xt = *(const float4*)(x + (long long)dst * E_HID + lane * 4);
    float p = (xs.x + rr.x) * xt.x + (xs.y + rr.y) * xt.y
            + (xs.z + rr.z) * xt.z + (xs.w + rr.w) * xt.w;
#pragma unroll
    for (int o = 16; o; o >>= 1) p += __shfl_xor_sync(0xffffffffu, p, o);
    if (lane == 0) g_dp[e] = p;
}

// ---------------------------------------------------------------------------
// K3: global max of g_dp
// ---------------------------------------------------------------------------
__global__ void k_max() {
    float m = -3.4e38f;
    int i = blockIdx.x * blockDim.x + threadIdx.x;
    int stride = gridDim.x * blockDim.x;
    for (int j = i; j < N_EDGES; j += stride) m = fmaxf(m, g_dp[j]);
#pragma unroll
    for (int o = 16; o; o >>= 1) m = fmaxf(m, __shfl_xor_sync(0xffffffffu, m, o));
    __shared__ float sm[32];
    if ((threadIdx.x & 31) == 0) sm[threadIdx.x >> 5] = m;
    __syncthreads();
    if (threadIdx.x < 32) {
        m = (threadIdx.x < (blockDim.x >> 5)) ? sm[threadIdx.x] : -3.4e38f;
#pragma unroll
        for (int o = 16; o; o >>= 1) m = fmaxf(m, __shfl_xor_sync(0xffffffffu, m, o));
        if (threadIdx.x == 0) atomicMax(&g_max_bits, enc_f(m));
    }
}

// ---------------------------------------------------------------------------
// K4: softmax denominator sum(exp(dp - max))
// ---------------------------------------------------------------------------
__global__ void k_sum() {
    float m = dec_f(g_max_bits);
    float s = 0.f;
    int i = blockIdx.x * blockDim.x + threadIdx.x;
    int stride = gridDim.x * blockDim.x;
    for (int j = i; j < N_EDGES; j += stride) s += __expf(g_dp[j] - m);
#pragma unroll
    for (int o = 16; o; o >>= 1) s += __shfl_xor_sync(0xffffffffu, s, o);
    __shared__ float sm[32];
    if ((threadIdx.x & 31) == 0) sm[threadIdx.x >> 5] = s;
    __syncthreads();
    if (threadIdx.x < 32) {
        s = (threadIdx.x < (blockDim.x >> 5)) ? sm[threadIdx.x] : 0.f;
#pragma unroll
        for (int o = 16; o; o >>= 1) s += __shfl_xor_sync(0xffffffffu, s, o);
        if (threadIdx.x == 0) atomicAdd(&g_sum, s);
    }
}

// ---------------------------------------------------------------------------
// K5: weighted scatter-add. One warp per edge; one red.global.add.v4.f32
// per lane (4x fewer RED instructions than scalar atomicAdd).
// ---------------------------------------------------------------------------
__global__ void k_scatter(const float* __restrict__ x,
                          const int* __restrict__ ei,
                          const int* __restrict__ et,
                          float* __restrict__ out) {
    int e = (int)(((long long)blockIdx.x * blockDim.x + threadIdx.x) >> 5);
    int lane = threadIdx.x & 31;
    if (e >= N_EDGES) return;
    float m = dec_f(g_max_bits);
    float inv = 1.0f / g_sum;
    float coef = __expf(g_dp[e] - m) * inv;
    int src = ei[e];
    int dst = ei[N_EDGES + e];
    int r = et[e];
    const float4 xs = *(const float4*)(x + (long long)src * E_HID + lane * 4);
    const float4 rr = *(const float4*)(g_remb + (long long)r * E_HID + lane * 4);
    float* p = out + (long long)dst * E_HID + lane * 4;
    red_add_v4(p, coef * (xs.x + rr.x), coef * (xs.y + rr.y),
                  coef * (xs.z + rr.z), coef * (xs.w + rr.w));
}

// ---------------------------------------------------------------------------
// K6: in-place ReLU on x_e (float4)
// ---------------------------------------------------------------------------
__global__ void k_relu(float* __restrict__ out) {
    int i = blockIdx.x * blockDim.x + threadIdx.x;
    int stride = gridDim.x * blockDim.x;
    float4* o4 = (float4*)out;
    for (int j = i; j < (N_NODES * E_HID) / 4; j += stride) {
        float4 v = o4[j];
        v.x = fmaxf(v.x, 0.f); v.y = fmaxf(v.y, 0.f);
        v.z = fmaxf(v.z, 0.f); v.w = fmaxf(v.w, 0.f);
        o4[j] = v;
    }
}

extern "C" void kernel_launch(void* const* d_in, const int* in_sizes, int n_in,
                              void* d_out, int out_size) {
    const float* x       = (const float*)d_in[0];   // [50000,128] f32
    const int*   ei      = (const int*)d_in[1];     // [2,600000] int32
    const int*   et      = (const int*)d_in[2];     // [600000] int32
    const float* rel_emb = (const float*)d_in[3];   // [500,128]
    const float* res_att = (const float*)d_in[4];   // [600000]
    const float* ww_w    = (const float*)d_in[5];   // [128,128]
    const float* rel_w   = (const float*)d_in[6];   // [128,128]
    float* out = (float*)d_out;

    (void)in_sizes; (void)n_in; (void)out_size;

    k_init<<<2048, 256>>>(out, res_att);
    k_rel<<<REL_NUM, E_HID>>>(rel_emb, ww_w, rel_w, out);

    const int edge_blocks = (N_EDGES * 32 + 255) / 256;  // warp per edge
    k_dp<<<edge_blocks, 256>>>(x, ei, et);
    k_max<<<512, 256>>>();
    k_sum<<<512, 256>>>();
    k_scatter<<<edge_blocks, 256>>>(x, ei, et, out);
    k_relu<<<2048, 256>>>(out);
}